// round 9
// baseline (speedup 1.0000x reference)
#include <cuda_runtime.h>
#include <cuda_bf16.h>
#include <cstdint>
#include <cstddef>

#define NROWS 8192
#define INDIM 2029
#define HW 2112   // padded plane width: 128(T) + 384(A) + 1600(V)

// Scratch (device globals — no allocation allowed)
__device__ __align__(16) __nv_bfloat16 g_h_hi[NROWS * HW];
__device__ __align__(16) __nv_bfloat16 g_h_lo[NROWS * HW];
__device__ __align__(16) __nv_bfloat16 g_ws[9 * 128 * 4800];   // per-seg B' = [bh|bh|bl]
__device__ __align__(16) __nv_bfloat16 g_wln[128 * 1152];      // Wln B' = [bh|bh|bl]
__device__ float g_qkv[NROWS * 1152];                          // [n][Vq Vk Vv Aq Ak Av Tq Tk Tv]
__device__ float g_qkv2[NROWS * 384];                          // V segs, K-chunks [38,75) partial
__device__ float g_attp[2 * NROWS * 384];                      // j-half partials of att
__device__ __align__(16) __nv_bfloat16 g_att_hi[NROWS * 384];  // [n][T|A|V] hi
__device__ __align__(16) __nv_bfloat16 g_att_lo[NROWS * 384];  // [n][T|A|V] lo

struct WPtrs { const float* w[9]; };

__device__ __forceinline__ float ex2f(float x) {
    float r; asm("ex2.approx.f32 %0, %1;" : "=f"(r) : "f"(x)); return r;
}
__device__ __forceinline__ uint32_t smem_u32(const void* p) {
    uint32_t a;
    asm("{ .reg .u64 t; cvta.to.shared.u64 t, %1; cvt.u32.u64 %0, t; }" : "=r"(a) : "l"(p));
    return a;
}
__device__ __forceinline__ void mma16816(float* c, const uint32_t* a, const uint32_t* b) {
    asm volatile(
        "mma.sync.aligned.m16n8k16.row.col.f32.bf16.bf16.f32 "
        "{%0,%1,%2,%3}, {%4,%5,%6,%7}, {%8,%9}, {%0,%1,%2,%3};"
        : "+f"(c[0]), "+f"(c[1]), "+f"(c[2]), "+f"(c[3])
        : "r"(a[0]), "r"(a[1]), "r"(a[2]), "r"(a[3]), "r"(b[0]), "r"(b[1]));
}
__device__ __forceinline__ void ldsm_x4(uint32_t* r, uint32_t addr) {
    asm volatile("ldmatrix.sync.aligned.m8n8.x4.shared.b16 {%0,%1,%2,%3}, [%4];"
        : "=r"(r[0]), "=r"(r[1]), "=r"(r[2]), "=r"(r[3]) : "r"(addr));
}
__device__ __forceinline__ void cp16(uint32_t d, const void* s) {
    asm volatile("cp.async.cg.shared.global [%0], [%1], 16;" :: "r"(d), "l"(s));
}
__device__ __forceinline__ void cp_commit() { asm volatile("cp.async.commit_group;" ::: "memory"); }
__device__ __forceinline__ void cp_wait1()  { asm volatile("cp.async.wait_group 1;" ::: "memory"); }

// ---------------------------------------------------------------------------
// Precompute: h -> per-unit hi/lo bf16 planes (zero-padded widths 128/384/1600)
// ---------------------------------------------------------------------------
__global__ __launch_bounds__(256)
void conv_h_kernel(const float* __restrict__ h) {
    const int n = blockIdx.x;
    for (int col = threadIdx.x; col < HW; col += 256) {
        int off, local, F;
        if (col < 128)      { off = 0;   local = col;       F = 100; }
        else if (col < 512) { off = 100; local = col - 128; F = 342; }
        else                { off = 442; local = col - 512; F = 1587; }
        float v = (local < F) ? __ldg(h + (size_t)n * INDIM + off + local) : 0.0f;
        __nv_bfloat16 hi = __float2bfloat16(v);
        __nv_bfloat16 lo = __float2bfloat16(v - __bfloat162float(hi));
        g_h_hi[(size_t)n * HW + col] = hi;
        g_h_lo[(size_t)n * HW + col] = lo;
    }
}

// ---------------------------------------------------------------------------
// Precompute weights: B' = [bh | bh | bl] per seg (and Wln as seg 9)
// ---------------------------------------------------------------------------
__global__ __launch_bounds__(256)
void conv_w_kernel(WPtrs wp, const float* __restrict__ Wln) {
    const int Fs[10]  = {1587,1587,1587, 342,342,342, 100,100,100, 384};
    const int Fps[10] = {1600,1600,1600, 384,384,384, 128,128,128, 384};
    const int d = blockIdx.x, t = blockIdx.y;
    const int F = Fs[t], Fp = Fps[t];
    const float* W = (t < 9) ? wp.w[t] : Wln;
    __nv_bfloat16* dst = (t < 9) ? (g_ws + (size_t)t * 128 * 4800 + (size_t)d * 3 * Fp)
                                 : (g_wln + (size_t)d * 1152);
    for (int k = threadIdx.x; k < 3 * Fp; k += 256) {
        int p = k / Fp, col = k - p * Fp;
        float v = (col < F) ? __ldg(W + (size_t)d * F + col) : 0.0f;
        __nv_bfloat16 hi = __float2bfloat16(v);
        if (p == 2) dst[k] = __float2bfloat16(v - __bfloat162float(hi));
        else        dst[k] = hi;
    }
}

// ---------------------------------------------------------------------------
// Plain bf16 GEMM: C[128 x 128] = A'[128 x 3Kp] * B'[128 x 3Kp]^T (+ bias),
// over chunk range [c0, c1). A' planes: [hi | lo | hi] (selected in loader);
// B' physically [bh|bh|bl]. cp.async 3-stage pipeline, ldmatrix fragments,
// smem row stride 144B (LDSM phase banks 4i mod 32 -> conflict-free).
// ---------------------------------------------------------------------------
#define ROWB 144
#define TILEB (128 * ROWB)
#define STAGEB (2 * TILEB)
#define GEMM_SMEM (3 * STAGEB)   // 110592

__device__ __forceinline__ void gemm_bf16_128(
    const __nv_bfloat16* __restrict__ Ahi, const __nv_bfloat16* __restrict__ Alo,
    int sA, int Kp,
    const __nv_bfloat16* __restrict__ B, int ldb,
    float* __restrict__ C, int ldc, const float* __restrict__ bias, int n0,
    int c0, int c1)
{
    extern __shared__ __align__(16) char dsm[];
    const uint32_t sbase = smem_u32(dsm);
    const int tid = threadIdx.x;
    const int lane = tid & 31, wid = tid >> 5;
    const int wm = wid & 3, wn = wid >> 2;
    const int g4 = lane >> 2, tq = lane & 3;
    const int lr = tid >> 1;
    const int c8 = (tid & 1) * 4;

    const int Kc = Kp >> 6;      // 64-wide chunks per plane
    const int NC = c1 - c0;

    // ldmatrix lane-address components
    const uint32_t a_off = (uint32_t)(wm * 32 + ((lane >> 3) & 1) * 8 + (lane & 7)) * ROWB
                           + ((lane >> 4) & 1) * 16;
    const uint32_t b_off = (uint32_t)(wn * 64 + ((lane >> 4) & 1) * 8 + (lane & 7)) * ROWB
                           + ((lane >> 3) & 1) * 16;

    float acc[2][8][4];
#pragma unroll
    for (int t = 0; t < 2; t++)
#pragma unroll
        for (int nt = 0; nt < 8; nt++)
#pragma unroll
            for (int i = 0; i < 4; i++) acc[t][nt][i] = 0.0f;

    auto issue = [&](int c, int st) {
        int pk = c / Kc;
        int cb = (c - pk * Kc) << 6;
        const __nv_bfloat16* As = ((pk == 1) ? Alo : Ahi)
                                  + (size_t)(n0 + lr) * sA + cb + c8 * 8;
        const __nv_bfloat16* Bs = B + (size_t)lr * ldb + (c << 6) + c8 * 8;
        uint32_t ab = sbase + st * STAGEB + lr * ROWB + c8 * 16;
        uint32_t bb = ab + TILEB;
#pragma unroll
        for (int i = 0; i < 4; i++) {
            cp16(ab + i * 16, As + i * 8);
            cp16(bb + i * 16, Bs + i * 8);
        }
        cp_commit();
    };

    issue(c0, 0);
    if (NC > 1) issue(c0 + 1, 1); else cp_commit();

    for (int ci = 0; ci < NC; ci++) {
        cp_wait1();
        __syncthreads();

        const uint32_t sa = sbase + (ci % 3) * STAGEB;
        const uint32_t aaddr = sa + a_off;
        const uint32_t baddr = sa + TILEB + b_off;
#pragma unroll
        for (int kk = 0; kk < 4; kk++) {
            uint32_t a[2][4];
            ldsm_x4(a[0], aaddr + kk * 32);
            ldsm_x4(a[1], aaddr + 16 * ROWB + kk * 32);
#pragma unroll
            for (int p = 0; p < 4; p++) {
                uint32_t b[4];
                ldsm_x4(b, baddr + p * 16 * ROWB + kk * 32);
                mma16816(acc[0][2 * p],     a[0], b);
                mma16816(acc[1][2 * p],     a[1], b);
                mma16816(acc[0][2 * p + 1], a[0], b + 2);
                mma16816(acc[1][2 * p + 1], a[1], b + 2);
            }
        }

        if (ci + 2 < NC) issue(c0 + ci + 2, (ci + 2) % 3);
        else cp_commit();   // empty group keeps wait_group bookkeeping consistent
    }

#pragma unroll
    for (int t = 0; t < 2; t++)
#pragma unroll
        for (int nt = 0; nt < 8; nt++) {
            int gm = n0 + wm * 32 + t * 16 + g4;
            int gn = wn * 64 + nt * 8 + tq * 2;
            float bx = 0.0f, by = 0.0f;
            if (bias) { bx = __ldg(bias + gn); by = __ldg(bias + gn + 1); }
            float2 v0 = make_float2(acc[t][nt][0] + bx, acc[t][nt][1] + by);
            float2 v1 = make_float2(acc[t][nt][2] + bx, acc[t][nt][3] + by);
            *(float2*)(C + (size_t)gm * ldc + gn) = v0;
            *(float2*)(C + (size_t)(gm + 8) * ldc + gn) = v1;
        }
}

// ---------------------------------------------------------------------------
// Kernel 1: QKV projections. V segs (s<3) split in K over blockIdx.z:
// z=0 -> chunks [0,38) into g_qkv; z=1 -> chunks [38,75) into g_qkv2.
// ---------------------------------------------------------------------------
__global__ __launch_bounds__(256, 2)
void qkv_mma_kernel() {
    const int Fps[9] = {1600,1600,1600, 384,384,384, 128,128,128};
    const int ub[9]  = { 512, 512, 512, 128,128,128,   0,  0,  0};
    const int s = blockIdx.y, z = blockIdx.z;
    const int Fp = Fps[s];
    const int NC = 3 * (Fp >> 6);

    int c0 = 0, c1 = NC, ldc = 1152;
    float* C = g_qkv + s * 128;
    if (s < 3) {
        if (z == 0) c1 = 38;
        else { c0 = 38; C = g_qkv2 + s * 128; ldc = 384; }
    } else if (z == 1) {
        return;
    }
    gemm_bf16_128(g_h_hi + ub[s], g_h_lo + ub[s], HW, Fp,
                  g_ws + (size_t)s * 128 * 4800, 3 * Fp,
                  C, ldc, nullptr, blockIdx.x * 128, c0, c1);
}

// ---------------------------------------------------------------------------
// Kernel 2: attention, split over j. Block = (n, u, jhalf): 64 columns.
// E[128 x 64] fp32, stride 68 floats (conflict-free STS + LDS.128).
// u==0 (V) sums the two qkv K-partials. qs read as float4 broadcasts.
// ---------------------------------------------------------------------------
#define ESTR 68
#define ATTN_SMEM (1280 + 128 * ESTR * 4)   // 36096

__global__ __launch_bounds__(128)
void attn_kernel() {
    extern __shared__ __align__(16) char dsm[];
    float* qs = (float*)dsm;                  // 128 f32
    float* zp = (float*)(dsm + 512);          // 128 f32 partial Z
    float* w  = (float*)(dsm + 1024);         // 64 f32
    float* E  = (float*)(dsm + 1280);         // 128 x 68 f32

    const int n    = blockIdx.x;
    const int u    = blockIdx.y;   // 0=V, 1=A, 2=T (qkv seg order)
    const int half = blockIdx.z;   // j in [half*64, half*64+64)
    const int t  = threadIdx.x;
    const int j  = t & 63;
    const int ih = t >> 6;

    const float* base  = g_qkv  + (size_t)n * 1152 + u * 384;
    const float* base2 = g_qkv2 + (size_t)n * 384;

    // log2(e) / sqrt(128)
    const float scale = 1.4426950408889634f / 11.313708498984761f;
    float qraw = base[t];
    float kraw = base[128 + half * 64 + j];
    if (u == 0) {
        qraw += base2[t];
        kraw += base2[128 + half * 64 + j];
    }
    qs[t] = qraw * scale;
    const float kj = kraw;
    __syncthreads();

    // Phase 1: E columns + partial Z; qs read as 16B broadcasts
    float z0 = 0.0f, z1 = 0.0f, z2 = 0.0f, z3 = 0.0f;
    const int i0 = ih * 64;
    const float4* qs4 = (const float4*)(qs + i0);
    float* Ecol = E + (size_t)i0 * ESTR + j;
#pragma unroll
    for (int q = 0; q < 16; q++) {
        float4 qv = qs4[q];
        float e0 = ex2f(qv.x * kj);
        float e1 = ex2f(qv.y * kj);
        float e2 = ex2f(qv.z * kj);
        float e3 = ex2f(qv.w * kj);
        Ecol[(q * 4 + 0) * ESTR] = e0;
        Ecol[(q * 4 + 1) * ESTR] = e1;
        Ecol[(q * 4 + 2) * ESTR] = e2;
        Ecol[(q * 4 + 3) * ESTR] = e3;
        z0 += e0; z1 += e1; z2 += e2; z3 += e3;
    }
    zp[t] = (z0 + z1) + (z2 + z3);
    __syncthreads();
    if (t < 64) {
        float Z = zp[t] + zp[t + 64];
        float vraw = base[256 + half * 64 + t];
        if (u == 0) vraw += base2[256 + half * 64 + t];
        w[t] = vraw / Z;
    }
    __syncthreads();

    // Phase 2: row dot (thread = output row i = t), 16 float4 pairs
    float o0 = 0.0f, o1 = 0.0f, o2 = 0.0f, o3 = 0.0f;
    const float4* Er = (const float4*)(E + t * ESTR);
    const float4* w4 = (const float4*)w;
#pragma unroll
    for (int q = 0; q < 16; q++) {
        float4 e4 = Er[q];
        float4 wv = w4[q];
        o0 += e4.x * wv.x;
        o1 += e4.y * wv.y;
        o2 += e4.z * wv.z;
        o3 += e4.w * wv.w;
    }
    float o = (o0 + o1) + (o2 + o3);

    const int attoff = (2 - u) * 128;   // att layout [T|A|V]
    g_attp[(size_t)half * (NROWS * 384) + (size_t)n * 384 + attoff + t] = o;
}

// ---------------------------------------------------------------------------
// Kernel 2b: sum the two j-half partials, emit att hi/lo bf16 planes.
// ---------------------------------------------------------------------------
__global__ __launch_bounds__(256)
void att_fix_kernel() {
    const int idx = blockIdx.x * 256 + threadIdx.x;   // NROWS*384 total
    float o = g_attp[idx] + g_attp[idx + NROWS * 384];
    __nv_bfloat16 hi = __float2bfloat16(o);
    __nv_bfloat16 lo = __float2bfloat16(o - __bfloat162float(hi));
    g_att_hi[idx] = hi;
    g_att_lo[idx] = lo;
}

// ---------------------------------------------------------------------------
// Kernel 3: out = att @ Wln.T + bln (plain bf16 GEMM, K' = 1152)
// ---------------------------------------------------------------------------
__global__ __launch_bounds__(256, 2)
void out_mma_kernel(const float* __restrict__ bln, float* __restrict__ out) {
    gemm_bf16_128(g_att_hi, g_att_lo, 384, 384, g_wln, 1152,
                  out, 128, bln, blockIdx.x * 128, 0, 18);
}

// ---------------------------------------------------------------------------
// Input order: 0 g, 1 h, 2 WqT, 3 WkT, 4 WvT, 5 WqA, 6 WkA, 7 WvA,
//              8 WqV, 9 WkV, 10 WvV, 11 Wln, 12 bln
// ---------------------------------------------------------------------------
extern "C" void kernel_launch(void* const* d_in, const int* in_sizes, int n_in,
                              void* d_out, int out_size) {
    const float* h = (const float*)d_in[1];
    WPtrs wp;
    wp.w[0] = (const float*)d_in[8];   // WqV
    wp.w[1] = (const float*)d_in[9];   // WkV
    wp.w[2] = (const float*)d_in[10];  // WvV
    wp.w[3] = (const float*)d_in[5];   // WqA
    wp.w[4] = (const float*)d_in[6];   // WkA
    wp.w[5] = (const float*)d_in[7];   // WvA
    wp.w[6] = (const float*)d_in[2];   // WqT
    wp.w[7] = (const float*)d_in[3];   // WkT
    wp.w[8] = (const float*)d_in[4];   // WvT
    const float* Wln = (const float*)d_in[11];
    const float* bln = (const float*)d_in[12];

    conv_h_kernel<<<NROWS, 256>>>(h);
    conv_w_kernel<<<dim3(128, 10), 256>>>(wp, Wln);

    cudaFuncSetAttribute(qkv_mma_kernel, cudaFuncAttributeMaxDynamicSharedMemorySize,
                         GEMM_SMEM);
    qkv_mma_kernel<<<dim3(64, 9, 2), 256, GEMM_SMEM>>>();

    cudaFuncSetAttribute(attn_kernel, cudaFuncAttributeMaxDynamicSharedMemorySize,
                         ATTN_SMEM);
    attn_kernel<<<dim3(NROWS, 3, 2), 128, ATTN_SMEM>>>();

    att_fix_kernel<<<(NROWS * 384) / 256, 256>>>();

    cudaFuncSetAttribute(out_mma_kernel, cudaFuncAttributeMaxDynamicSharedMemorySize,
                         GEMM_SMEM);
    out_mma_kernel<<<64, 256, GEMM_SMEM>>>(bln, (float*)d_out);
}

// round 10
// speedup vs baseline: 1.2088x; 1.2088x over previous
#include <cuda_runtime.h>
#include <cuda_bf16.h>
#include <cstdint>
#include <cstddef>

#define NROWS 8192
#define INDIM 2029
#define HW 2112   // padded plane width: 128(T) + 384(A) + 1600(V)

// Scratch (device globals — no allocation allowed)
__device__ __align__(16) __nv_bfloat16 g_h_hi[NROWS * HW];
__device__ __align__(16) __nv_bfloat16 g_h_lo[NROWS * HW];
__device__ __align__(16) __nv_bfloat16 g_ws[9 * 128 * 4800];   // per-seg B' = [bh|bh|bl]
__device__ __align__(16) __nv_bfloat16 g_wln[128 * 1152];      // Wln B' = [bh|bh|bl]
__device__ float g_qkv[NROWS * 1152];                          // [n][Vq Vk Vv Aq Ak Av Tq Tk Tv]
__device__ float g_qkv2[NROWS * 384];                          // V segs, K-chunks [38,75) partial
__device__ float g_attp[4 * NROWS * 384];                      // j-quarter partials of att
__device__ __align__(16) __nv_bfloat16 g_att_hi[NROWS * 384];  // [n][T|A|V] hi
__device__ __align__(16) __nv_bfloat16 g_att_lo[NROWS * 384];  // [n][T|A|V] lo

struct WPtrs { const float* w[9]; };

__device__ __forceinline__ float ex2f(float x) {
    float r; asm("ex2.approx.f32 %0, %1;" : "=f"(r) : "f"(x)); return r;
}
__device__ __forceinline__ uint32_t smem_u32(const void* p) {
    uint32_t a;
    asm("{ .reg .u64 t; cvta.to.shared.u64 t, %1; cvt.u32.u64 %0, t; }" : "=r"(a) : "l"(p));
    return a;
}
__device__ __forceinline__ void mma16816(float* c, const uint32_t* a, const uint32_t* b) {
    asm volatile(
        "mma.sync.aligned.m16n8k16.row.col.f32.bf16.bf16.f32 "
        "{%0,%1,%2,%3}, {%4,%5,%6,%7}, {%8,%9}, {%0,%1,%2,%3};"
        : "+f"(c[0]), "+f"(c[1]), "+f"(c[2]), "+f"(c[3])
        : "r"(a[0]), "r"(a[1]), "r"(a[2]), "r"(a[3]), "r"(b[0]), "r"(b[1]));
}
__device__ __forceinline__ void ldsm_x4(uint32_t* r, uint32_t addr) {
    asm volatile("ldmatrix.sync.aligned.m8n8.x4.shared.b16 {%0,%1,%2,%3}, [%4];"
        : "=r"(r[0]), "=r"(r[1]), "=r"(r[2]), "=r"(r[3]) : "r"(addr));
}
__device__ __forceinline__ void cp16(uint32_t d, const void* s) {
    asm volatile("cp.async.cg.shared.global [%0], [%1], 16;" :: "r"(d), "l"(s));
}
__device__ __forceinline__ void cp_commit() { asm volatile("cp.async.commit_group;" ::: "memory"); }
__device__ __forceinline__ void cp_wait1()  { asm volatile("cp.async.wait_group 1;" ::: "memory"); }

// ---------------------------------------------------------------------------
// Precompute: h -> per-unit hi/lo bf16 planes (zero-padded widths 128/384/1600)
// ---------------------------------------------------------------------------
__global__ __launch_bounds__(256)
void conv_h_kernel(const float* __restrict__ h) {
    const int n = blockIdx.x;
    for (int col = threadIdx.x; col < HW; col += 256) {
        int off, local, F;
        if (col < 128)      { off = 0;   local = col;       F = 100; }
        else if (col < 512) { off = 100; local = col - 128; F = 342; }
        else                { off = 442; local = col - 512; F = 1587; }
        float v = (local < F) ? __ldg(h + (size_t)n * INDIM + off + local) : 0.0f;
        __nv_bfloat16 hi = __float2bfloat16(v);
        __nv_bfloat16 lo = __float2bfloat16(v - __bfloat162float(hi));
        g_h_hi[(size_t)n * HW + col] = hi;
        g_h_lo[(size_t)n * HW + col] = lo;
    }
}

// ---------------------------------------------------------------------------
// Precompute weights: B' = [bh | bh | bl] per seg (and Wln as seg 9)
// ---------------------------------------------------------------------------
__global__ __launch_bounds__(256)
void conv_w_kernel(WPtrs wp, const float* __restrict__ Wln) {
    const int Fs[10]  = {1587,1587,1587, 342,342,342, 100,100,100, 384};
    const int Fps[10] = {1600,1600,1600, 384,384,384, 128,128,128, 384};
    const int d = blockIdx.x, t = blockIdx.y;
    const int F = Fs[t], Fp = Fps[t];
    const float* W = (t < 9) ? wp.w[t] : Wln;
    __nv_bfloat16* dst = (t < 9) ? (g_ws + (size_t)t * 128 * 4800 + (size_t)d * 3 * Fp)
                                 : (g_wln + (size_t)d * 1152);
    for (int k = threadIdx.x; k < 3 * Fp; k += 256) {
        int p = k / Fp, col = k - p * Fp;
        float v = (col < F) ? __ldg(W + (size_t)d * F + col) : 0.0f;
        __nv_bfloat16 hi = __float2bfloat16(v);
        if (p == 2) dst[k] = __float2bfloat16(v - __bfloat162float(hi));
        else        dst[k] = hi;
    }
}

// ---------------------------------------------------------------------------
// Plain bf16 GEMM, 512 threads: C[128 x 128] = A'[128 x 3Kp] * B'[128 x 3Kp]^T
// (+ bias), over chunk range [c0, c1). A' planes: [hi | lo | hi] (selected in
// loader); B' physically [bh|bh|bl]. 16 warps, warp tile 32x32 (acc = 32 regs).
// cp.async 3-stage pipeline, ldmatrix fragments, smem row stride 144B.
// ---------------------------------------------------------------------------
#define ROWB 144
#define TILEB (128 * ROWB)
#define STAGEB (2 * TILEB)
#define GEMM_SMEM (3 * STAGEB)   // 110592

__device__ __forceinline__ void gemm_bf16_128(
    const __nv_bfloat16* __restrict__ Ahi, const __nv_bfloat16* __restrict__ Alo,
    int sA, int Kp,
    const __nv_bfloat16* __restrict__ B, int ldb,
    float* __restrict__ C, int ldc, const float* __restrict__ bias, int n0,
    int c0, int c1)
{
    extern __shared__ __align__(16) char dsm[];
    const uint32_t sbase = smem_u32(dsm);
    const int tid = threadIdx.x;
    const int lane = tid & 31, wid = tid >> 5;       // 16 warps
    const int wm = wid & 3, wn = wid >> 2;           // 4 x 4 warp grid
    const int g4 = lane >> 2, tq = lane & 3;
    const int lr = tid >> 2;                          // loader row 0..127
    const int q4 = tid & 3;                           // loader quarter

    const int Kc = Kp >> 6;      // 64-wide chunks per plane
    const int NC = c1 - c0;

    // ldmatrix lane-address components (x4: rows of two 8x8 pairs + klo/khi)
    const uint32_t a_off = (uint32_t)(wm * 32 + ((lane >> 3) & 1) * 8 + (lane & 7)) * ROWB
                           + ((lane >> 4) & 1) * 16;
    const uint32_t b_off = (uint32_t)(wn * 32 + ((lane >> 4) & 1) * 8 + (lane & 7)) * ROWB
                           + ((lane >> 3) & 1) * 16;

    float acc[2][4][4];
#pragma unroll
    for (int t = 0; t < 2; t++)
#pragma unroll
        for (int nt = 0; nt < 4; nt++)
#pragma unroll
            for (int i = 0; i < 4; i++) acc[t][nt][i] = 0.0f;

    auto issue = [&](int c, int st) {
        int pk = c / Kc;
        int cb = (c - pk * Kc) << 6;
        const __nv_bfloat16* As = ((pk == 1) ? Alo : Ahi)
                                  + (size_t)(n0 + lr) * sA + cb + q4 * 16;
        const __nv_bfloat16* Bs = B + (size_t)lr * ldb + (c << 6) + q4 * 16;
        uint32_t ab = sbase + st * STAGEB + lr * ROWB + q4 * 32;
        uint32_t bb = ab + TILEB;
#pragma unroll
        for (int i = 0; i < 2; i++) {
            cp16(ab + i * 16, As + i * 8);
            cp16(bb + i * 16, Bs + i * 8);
        }
        cp_commit();
    };

    issue(c0, 0);
    if (NC > 1) issue(c0 + 1, 1); else cp_commit();

    for (int ci = 0; ci < NC; ci++) {
        cp_wait1();
        __syncthreads();

        const uint32_t sa = sbase + (ci % 3) * STAGEB;
        const uint32_t aaddr = sa + a_off;
        const uint32_t baddr = sa + TILEB + b_off;
#pragma unroll
        for (int kk = 0; kk < 4; kk++) {
            uint32_t a[2][4], b[2][4];
            ldsm_x4(a[0], aaddr + kk * 32);
            ldsm_x4(a[1], aaddr + 16 * ROWB + kk * 32);
            ldsm_x4(b[0], baddr + kk * 32);
            ldsm_x4(b[1], baddr + 16 * ROWB + kk * 32);
#pragma unroll
            for (int nt = 0; nt < 4; nt++) {
                mma16816(acc[0][nt], a[0], b[nt >> 1] + (nt & 1) * 2);
                mma16816(acc[1][nt], a[1], b[nt >> 1] + (nt & 1) * 2);
            }
        }

        if (ci + 2 < NC) issue(c0 + ci + 2, (ci + 2) % 3);
        else cp_commit();   // empty group keeps wait_group bookkeeping consistent
    }

#pragma unroll
    for (int t = 0; t < 2; t++)
#pragma unroll
        for (int nt = 0; nt < 4; nt++) {
            int gm = n0 + wm * 32 + t * 16 + g4;
            int gn = wn * 32 + nt * 8 + tq * 2;
            float bx = 0.0f, by = 0.0f;
            if (bias) { bx = __ldg(bias + gn); by = __ldg(bias + gn + 1); }
            float2 v0 = make_float2(acc[t][nt][0] + bx, acc[t][nt][1] + by);
            float2 v1 = make_float2(acc[t][nt][2] + bx, acc[t][nt][3] + by);
            *(float2*)(C + (size_t)gm * ldc + gn) = v0;
            *(float2*)(C + (size_t)(gm + 8) * ldc + gn) = v1;
        }
}

// ---------------------------------------------------------------------------
// Kernel 1: QKV projections. V segs (s<3) split in K over blockIdx.z:
// z=0 -> chunks [0,38) into g_qkv; z=1 -> chunks [38,75) into g_qkv2.
// ---------------------------------------------------------------------------
__global__ __launch_bounds__(512, 2)
void qkv_mma_kernel() {
    const int Fps[9] = {1600,1600,1600, 384,384,384, 128,128,128};
    const int ub[9]  = { 512, 512, 512, 128,128,128,   0,  0,  0};
    const int s = blockIdx.y, z = blockIdx.z;
    const int Fp = Fps[s];
    const int NC = 3 * (Fp >> 6);

    int c0 = 0, c1 = NC, ldc = 1152;
    float* C = g_qkv + s * 128;
    if (s < 3) {
        if (z == 0) c1 = 38;
        else { c0 = 38; C = g_qkv2 + s * 128; ldc = 384; }
    } else if (z == 1) {
        return;
    }
    gemm_bf16_128(g_h_hi + ub[s], g_h_lo + ub[s], HW, Fp,
                  g_ws + (size_t)s * 128 * 4800, 3 * Fp,
                  C, ldc, nullptr, blockIdx.x * 128, c0, c1);
}

// ---------------------------------------------------------------------------
// Kernel 2: attention, split over j quarters. Block = (n, u, jq): 32 columns.
// E[128 x 32] fp32, stride 36 floats (conflict-free STS + LDS.128).
// smem 19.7KB -> 11 CTAs/SM. u==0 (V) sums the two qkv K-partials.
// ---------------------------------------------------------------------------
#define ESTR 36
#define ATTN_SMEM (1280 + 128 * ESTR * 4)   // 19712

__global__ __launch_bounds__(128)
void attn_kernel() {
    extern __shared__ __align__(16) char dsm[];
    float* qs = (float*)dsm;                  // 128 f32
    float* zp = (float*)(dsm + 512);          // 128 f32 partial Z
    float* w  = (float*)(dsm + 1024);         // 32 f32
    float* E  = (float*)(dsm + 1280);         // 128 x 36 f32

    const int n  = blockIdx.x;
    const int u  = blockIdx.y;   // 0=V, 1=A, 2=T (qkv seg order)
    const int jq = blockIdx.z;   // j in [jq*32, jq*32+32)
    const int t  = threadIdx.x;
    const int j  = t & 31;
    const int ih = t >> 5;       // 0..3, i-range [ih*32, ih*32+32)

    const float* base  = g_qkv  + (size_t)n * 1152 + u * 384;
    const float* base2 = g_qkv2 + (size_t)n * 384;

    // log2(e) / sqrt(128)
    const float scale = 1.4426950408889634f / 11.313708498984761f;
    float qraw = base[t];
    float kraw = base[128 + jq * 32 + j];
    if (u == 0) {
        qraw += base2[t];
        kraw += base2[128 + jq * 32 + j];
    }
    qs[t] = qraw * scale;
    const float kj = kraw;
    __syncthreads();

    // Phase 1: E columns + partial Z; qs read as 16B broadcasts
    float z0 = 0.0f, z1 = 0.0f, z2 = 0.0f, z3 = 0.0f;
    const int i0 = ih * 32;
    const float4* qs4 = (const float4*)(qs + i0);
    float* Ecol = E + (size_t)i0 * ESTR + j;
#pragma unroll
    for (int q = 0; q < 8; q++) {
        float4 qv = qs4[q];
        float e0 = ex2f(qv.x * kj);
        float e1 = ex2f(qv.y * kj);
        float e2 = ex2f(qv.z * kj);
        float e3 = ex2f(qv.w * kj);
        Ecol[(q * 4 + 0) * ESTR] = e0;
        Ecol[(q * 4 + 1) * ESTR] = e1;
        Ecol[(q * 4 + 2) * ESTR] = e2;
        Ecol[(q * 4 + 3) * ESTR] = e3;
        z0 += e0; z1 += e1; z2 += e2; z3 += e3;
    }
    zp[t] = (z0 + z1) + (z2 + z3);
    __syncthreads();
    if (t < 32) {
        float Z = (zp[t] + zp[t + 32]) + (zp[t + 64] + zp[t + 96]);
        float vraw = base[256 + jq * 32 + t];
        if (u == 0) vraw += base2[256 + jq * 32 + t];
        w[t] = vraw / Z;
    }
    __syncthreads();

    // Phase 2: row dot (thread = output row i = t), 8 float4 pairs
    float o0 = 0.0f, o1 = 0.0f, o2 = 0.0f, o3 = 0.0f;
    const float4* Er = (const float4*)(E + t * ESTR);
    const float4* w4 = (const float4*)w;
#pragma unroll
    for (int q = 0; q < 8; q++) {
        float4 e4 = Er[q];
        float4 wv = w4[q];
        o0 += e4.x * wv.x;
        o1 += e4.y * wv.y;
        o2 += e4.z * wv.z;
        o3 += e4.w * wv.w;
    }
    float o = (o0 + o1) + (o2 + o3);

    const int attoff = (2 - u) * 128;   // att layout [T|A|V]
    g_attp[(size_t)jq * (NROWS * 384) + (size_t)n * 384 + attoff + t] = o;
}

// ---------------------------------------------------------------------------
// Kernel 2b: sum the four j-quarter partials, emit att hi/lo bf16 planes.
// ---------------------------------------------------------------------------
__global__ __launch_bounds__(256)
void att_fix_kernel() {
    const int idx = blockIdx.x * 256 + threadIdx.x;   // NROWS*384 total
    const int S = NROWS * 384;
    float o = (g_attp[idx] + g_attp[idx + S]) + (g_attp[idx + 2 * S] + g_attp[idx + 3 * S]);
    __nv_bfloat16 hi = __float2bfloat16(o);
    __nv_bfloat16 lo = __float2bfloat16(o - __bfloat162float(hi));
    g_att_hi[idx] = hi;
    g_att_lo[idx] = lo;
}

// ---------------------------------------------------------------------------
// Kernel 3: out = att @ Wln.T + bln (plain bf16 GEMM, K' = 1152)
// ---------------------------------------------------------------------------
__global__ __launch_bounds__(512, 2)
void out_mma_kernel(const float* __restrict__ bln, float* __restrict__ out) {
    gemm_bf16_128(g_att_hi, g_att_lo, 384, 384, g_wln, 1152,
                  out, 128, bln, blockIdx.x * 128, 0, 18);
}

// ---------------------------------------------------------------------------
// Input order: 0 g, 1 h, 2 WqT, 3 WkT, 4 WvT, 5 WqA, 6 WkA, 7 WvA,
//              8 WqV, 9 WkV, 10 WvV, 11 Wln, 12 bln
// ---------------------------------------------------------------------------
extern "C" void kernel_launch(void* const* d_in, const int* in_sizes, int n_in,
                              void* d_out, int out_size) {
    const float* h = (const float*)d_in[1];
    WPtrs wp;
    wp.w[0] = (const float*)d_in[8];   // WqV
    wp.w[1] = (const float*)d_in[9];   // WkV
    wp.w[2] = (const float*)d_in[10];  // WvV
    wp.w[3] = (const float*)d_in[5];   // WqA
    wp.w[4] = (const float*)d_in[6];   // WkA
    wp.w[5] = (const float*)d_in[7];   // WvA
    wp.w[6] = (const float*)d_in[2];   // WqT
    wp.w[7] = (const float*)d_in[3];   // WkT
    wp.w[8] = (const float*)d_in[4];   // WvT
    const float* Wln = (const float*)d_in[11];
    const float* bln = (const float*)d_in[12];

    conv_h_kernel<<<NROWS, 256>>>(h);
    conv_w_kernel<<<dim3(128, 10), 256>>>(wp, Wln);

    cudaFuncSetAttribute(qkv_mma_kernel, cudaFuncAttributeMaxDynamicSharedMemorySize,
                         GEMM_SMEM);
    qkv_mma_kernel<<<dim3(64, 9, 2), 512, GEMM_SMEM>>>();

    cudaFuncSetAttribute(attn_kernel, cudaFuncAttributeMaxDynamicSharedMemorySize,
                         ATTN_SMEM);
    attn_kernel<<<dim3(NROWS, 3, 4), 128, ATTN_SMEM>>>();

    att_fix_kernel<<<(NROWS * 384) / 256, 256>>>();

    cudaFuncSetAttribute(out_mma_kernel, cudaFuncAttributeMaxDynamicSharedMemorySize,
                         GEMM_SMEM);
    out_mma_kernel<<<64, 512, GEMM_SMEM>>>(bln, (float*)d_out);
}

// round 11
// speedup vs baseline: 1.2527x; 1.0363x over previous
#include <cuda_runtime.h>
#include <cuda_bf16.h>
#include <cstdint>
#include <cstddef>

#define NROWS 8192
#define INDIM 2029
#define HW 2112   // padded plane width: 128(T) + 384(A) + 1600(V)

// Scratch (device globals — no allocation allowed)
__device__ __align__(16) __nv_bfloat16 g_h_hi[NROWS * HW];
__device__ __align__(16) __nv_bfloat16 g_h_lo[NROWS * HW];
__device__ __align__(16) __nv_bfloat16 g_ws[9 * 128 * 4800];   // per-seg B' = [bh|bh|bl]
__device__ __align__(16) __nv_bfloat16 g_wln[128 * 1152];      // Wln B' = [bh|bh|bl]
__device__ float g_qkv[NROWS * 1152];                          // [n][Vq Vk Vv Aq Ak Av Tq Tk Tv]
__device__ float g_qkv2[NROWS * 384];                          // V segs, K-chunks [38,75) partial
__device__ __align__(16) float g_attp[4 * NROWS * 384];        // j-quarter partials of att
__device__ __align__(16) __nv_bfloat16 g_att_hi[NROWS * 384];  // [n][T|A|V] hi
__device__ __align__(16) __nv_bfloat16 g_att_lo[NROWS * 384];  // [n][T|A|V] lo

struct WPtrs { const float* w[9]; };

__device__ __forceinline__ float ex2f(float x) {
    float r; asm("ex2.approx.f32 %0, %1;" : "=f"(r) : "f"(x)); return r;
}
__device__ __forceinline__ uint32_t smem_u32(const void* p) {
    uint32_t a;
    asm("{ .reg .u64 t; cvta.to.shared.u64 t, %1; cvt.u32.u64 %0, t; }" : "=r"(a) : "l"(p));
    return a;
}
__device__ __forceinline__ void mma16816(float* c, const uint32_t* a, const uint32_t* b) {
    asm volatile(
        "mma.sync.aligned.m16n8k16.row.col.f32.bf16.bf16.f32 "
        "{%0,%1,%2,%3}, {%4,%5,%6,%7}, {%8,%9}, {%0,%1,%2,%3};"
        : "+f"(c[0]), "+f"(c[1]), "+f"(c[2]), "+f"(c[3])
        : "r"(a[0]), "r"(a[1]), "r"(a[2]), "r"(a[3]), "r"(b[0]), "r"(b[1]));
}
__device__ __forceinline__ void ldsm_x4(uint32_t* r, uint32_t addr) {
    asm volatile("ldmatrix.sync.aligned.m8n8.x4.shared.b16 {%0,%1,%2,%3}, [%4];"
        : "=r"(r[0]), "=r"(r[1]), "=r"(r[2]), "=r"(r[3]) : "r"(addr));
}
__device__ __forceinline__ void cp16(uint32_t d, const void* s) {
    asm volatile("cp.async.cg.shared.global [%0], [%1], 16;" :: "r"(d), "l"(s));
}
__device__ __forceinline__ void cp_commit() { asm volatile("cp.async.commit_group;" ::: "memory"); }
__device__ __forceinline__ void cp_wait1()  { asm volatile("cp.async.wait_group 1;" ::: "memory"); }

// ---------------------------------------------------------------------------
// Precompute: h -> per-unit hi/lo bf16 planes (zero-padded widths 128/384/1600)
// 4 cols per thread; STG.64 stores.
// ---------------------------------------------------------------------------
__global__ __launch_bounds__(256)
void conv_h_kernel(const float* __restrict__ h) {
    const int n = blockIdx.x;
    const float* hrow = h + (size_t)n * INDIM;
    for (int g = threadIdx.x; g < HW / 4; g += 256) {
        const int col = g * 4;
        int off, local0, F;
        if (col < 128)      { off = 0;   local0 = col;       F = 100; }
        else if (col < 512) { off = 100; local0 = col - 128; F = 342; }
        else                { off = 442; local0 = col - 512; F = 1587; }
        __nv_bfloat16 hi4[4], lo4[4];
#pragma unroll
        for (int e = 0; e < 4; e++) {
            int lc = local0 + e;
            float v = (lc < F) ? __ldg(hrow + off + lc) : 0.0f;
            __nv_bfloat16 hi = __float2bfloat16(v);
            hi4[e] = hi;
            lo4[e] = __float2bfloat16(v - __bfloat162float(hi));
        }
        *reinterpret_cast<uint2*>(&g_h_hi[(size_t)n * HW + col]) = *reinterpret_cast<uint2*>(hi4);
        *reinterpret_cast<uint2*>(&g_h_lo[(size_t)n * HW + col]) = *reinterpret_cast<uint2*>(lo4);
    }
}

// ---------------------------------------------------------------------------
// Precompute weights: B' = [bh | bh | bl] per seg (and Wln as seg 9)
// ---------------------------------------------------------------------------
__global__ __launch_bounds__(256)
void conv_w_kernel(WPtrs wp, const float* __restrict__ Wln) {
    const int Fs[10]  = {1587,1587,1587, 342,342,342, 100,100,100, 384};
    const int Fps[10] = {1600,1600,1600, 384,384,384, 128,128,128, 384};
    const int d = blockIdx.x, t = blockIdx.y;
    const int F = Fs[t], Fp = Fps[t];
    const float* W = (t < 9) ? wp.w[t] : Wln;
    __nv_bfloat16* dst = (t < 9) ? (g_ws + (size_t)t * 128 * 4800 + (size_t)d * 3 * Fp)
                                 : (g_wln + (size_t)d * 1152);
    for (int k = threadIdx.x; k < 3 * Fp; k += 256) {
        int p = k / Fp, col = k - p * Fp;
        float v = (col < F) ? __ldg(W + (size_t)d * F + col) : 0.0f;
        __nv_bfloat16 hi = __float2bfloat16(v);
        if (p == 2) dst[k] = __float2bfloat16(v - __bfloat162float(hi));
        else        dst[k] = hi;
    }
}

// ---------------------------------------------------------------------------
// Plain bf16 GEMM, 512 threads: C[128 x 128] = A'[128 x 3Kp] * B'[128 x 3Kp]^T
// (+ bias), over chunk range [c0, c1). A' planes: [hi | lo | hi] (selected in
// loader); B' physically [bh|bh|bl]. 16 warps, warp tile 32x32 (acc = 32 regs).
// cp.async 3-stage pipeline, ldmatrix fragments, smem row stride 144B.
// ---------------------------------------------------------------------------
#define ROWB 144
#define TILEB (128 * ROWB)
#define STAGEB (2 * TILEB)
#define GEMM_SMEM (3 * STAGEB)   // 110592

__device__ __forceinline__ void gemm_bf16_128(
    const __nv_bfloat16* __restrict__ Ahi, const __nv_bfloat16* __restrict__ Alo,
    int sA, int Kp,
    const __nv_bfloat16* __restrict__ B, int ldb,
    float* __restrict__ C, int ldc, const float* __restrict__ bias, int n0,
    int c0, int c1)
{
    extern __shared__ __align__(16) char dsm[];
    const uint32_t sbase = smem_u32(dsm);
    const int tid = threadIdx.x;
    const int lane = tid & 31, wid = tid >> 5;       // 16 warps
    const int wm = wid & 3, wn = wid >> 2;           // 4 x 4 warp grid
    const int g4 = lane >> 2, tq = lane & 3;
    const int lr = tid >> 2;                          // loader row 0..127
    const int q4 = tid & 3;                           // loader quarter

    const int Kc = Kp >> 6;      // 64-wide chunks per plane
    const int NC = c1 - c0;

    // ldmatrix lane-address components (x4: rows of two 8x8 pairs + klo/khi)
    const uint32_t a_off = (uint32_t)(wm * 32 + ((lane >> 3) & 1) * 8 + (lane & 7)) * ROWB
                           + ((lane >> 4) & 1) * 16;
    const uint32_t b_off = (uint32_t)(wn * 32 + ((lane >> 4) & 1) * 8 + (lane & 7)) * ROWB
                           + ((lane >> 3) & 1) * 16;

    float acc[2][4][4];
#pragma unroll
    for (int t = 0; t < 2; t++)
#pragma unroll
        for (int nt = 0; nt < 4; nt++)
#pragma unroll
            for (int i = 0; i < 4; i++) acc[t][nt][i] = 0.0f;

    auto issue = [&](int c, int st) {
        int pk = c / Kc;
        int cb = (c - pk * Kc) << 6;
        const __nv_bfloat16* As = ((pk == 1) ? Alo : Ahi)
                                  + (size_t)(n0 + lr) * sA + cb + q4 * 16;
        const __nv_bfloat16* Bs = B + (size_t)lr * ldb + (c << 6) + q4 * 16;
        uint32_t ab = sbase + st * STAGEB + lr * ROWB + q4 * 32;
        uint32_t bb = ab + TILEB;
#pragma unroll
        for (int i = 0; i < 2; i++) {
            cp16(ab + i * 16, As + i * 8);
            cp16(bb + i * 16, Bs + i * 8);
        }
        cp_commit();
    };

    issue(c0, 0);
    if (NC > 1) issue(c0 + 1, 1); else cp_commit();

    for (int ci = 0; ci < NC; ci++) {
        cp_wait1();
        __syncthreads();

        const uint32_t sa = sbase + (ci % 3) * STAGEB;
        const uint32_t aaddr = sa + a_off;
        const uint32_t baddr = sa + TILEB + b_off;
#pragma unroll
        for (int kk = 0; kk < 4; kk++) {
            uint32_t a[2][4], b[2][4];
            ldsm_x4(a[0], aaddr + kk * 32);
            ldsm_x4(a[1], aaddr + 16 * ROWB + kk * 32);
            ldsm_x4(b[0], baddr + kk * 32);
            ldsm_x4(b[1], baddr + 16 * ROWB + kk * 32);
#pragma unroll
            for (int nt = 0; nt < 4; nt++) {
                mma16816(acc[0][nt], a[0], b[nt >> 1] + (nt & 1) * 2);
                mma16816(acc[1][nt], a[1], b[nt >> 1] + (nt & 1) * 2);
            }
        }

        if (ci + 2 < NC) issue(c0 + ci + 2, (ci + 2) % 3);
        else cp_commit();   // empty group keeps wait_group bookkeeping consistent
    }

#pragma unroll
    for (int t = 0; t < 2; t++)
#pragma unroll
        for (int nt = 0; nt < 4; nt++) {
            int gm = n0 + wm * 32 + t * 16 + g4;
            int gn = wn * 32 + nt * 8 + tq * 2;
            float bx = 0.0f, by = 0.0f;
            if (bias) { bx = __ldg(bias + gn); by = __ldg(bias + gn + 1); }
            float2 v0 = make_float2(acc[t][nt][0] + bx, acc[t][nt][1] + by);
            float2 v1 = make_float2(acc[t][nt][2] + bx, acc[t][nt][3] + by);
            *(float2*)(C + (size_t)gm * ldc + gn) = v0;
            *(float2*)(C + (size_t)(gm + 8) * ldc + gn) = v1;
        }
}

// ---------------------------------------------------------------------------
// Kernel 1: QKV projections. V segs (s<3) split in K over blockIdx.z:
// z=0 -> chunks [0,38) into g_qkv; z=1 -> chunks [38,75) into g_qkv2.
// ---------------------------------------------------------------------------
__global__ __launch_bounds__(512, 2)
void qkv_mma_kernel() {
    const int Fps[9] = {1600,1600,1600, 384,384,384, 128,128,128};
    const int ub[9]  = { 512, 512, 512, 128,128,128,   0,  0,  0};
    const int s = blockIdx.y, z = blockIdx.z;
    const int Fp = Fps[s];
    const int NC = 3 * (Fp >> 6);

    int c0 = 0, c1 = NC, ldc = 1152;
    float* C = g_qkv + s * 128;
    if (s < 3) {
        if (z == 0) c1 = 38;
        else { c0 = 38; C = g_qkv2 + s * 128; ldc = 384; }
    } else if (z == 1) {
        return;
    }
    gemm_bf16_128(g_h_hi + ub[s], g_h_lo + ub[s], HW, Fp,
                  g_ws + (size_t)s * 128 * 4800, 3 * Fp,
                  C, ldc, nullptr, blockIdx.x * 128, c0, c1);
}

// ---------------------------------------------------------------------------
// Kernel 2: attention with register-resident E (no E smem at all).
// Block = (n, u, jq): 32 columns. Warp w's 32x32 block E[rows 32w..32w+31]
// [cols jq*32..+31] lives in registers: lane j computes row (j+s)&31 at c[s];
// column Z partial is lane-local; pre-scale by w_j; transpose-sum via shfl.
// ---------------------------------------------------------------------------
__global__ __launch_bounds__(128)
void attn_kernel() {
    __shared__ float zp[128];

    const int n  = blockIdx.x;
    const int u  = blockIdx.y;   // 0=V, 1=A, 2=T (qkv seg order)
    const int jq = blockIdx.z;   // j in [jq*32, jq*32+32)
    const int t    = threadIdx.x;
    const int lane = t & 31;

    const float* base  = g_qkv  + (size_t)n * 1152 + u * 384;
    const float* base2 = g_qkv2 + (size_t)n * 384;

    // log2(e) / sqrt(128)
    const float scale = 1.4426950408889634f / 11.313708498984761f;
    float qraw = base[t];                      // q for row i = t
    float kraw = base[128 + jq * 32 + lane];   // k for column j = jq*32+lane
    float vraw = base[256 + jq * 32 + lane];   // v for column j
    if (u == 0) {
        qraw += base2[t];
        kraw += base2[128 + jq * 32 + lane];
        vraw += base2[256 + jq * 32 + lane];
    }
    const float qown = qraw * scale;

    // Phase 1: lane computes its column over the warp's 32-row stripe,
    // row order rotated by lane: c[s] = E[(lane+s)&31][lane], plus column Z.
    float c[32];
    float z = 0.0f;
#pragma unroll
    for (int s = 0; s < 32; s++) {
        float qi = __shfl_sync(0xFFFFFFFFu, qown, (lane + s) & 31);
        float e = ex2f(qi * kraw);
        c[s] = e;
        z += e;
    }
    zp[t] = z;
    __syncthreads();

    // Full column Z (4 stripe partials), lane-local w_j = v_j / Z_j
    float Z = (zp[lane] + zp[lane + 32]) + (zp[lane + 64] + zp[lane + 96]);
    const float ws = vraw / Z;

    // Phase 2: transpose-sum. out_row r=lane: E[r][j]*w_j sits at lane j,
    // slot s = (r - j)&31  =>  round s reads from src = (lane - s)&31.
    float out = 0.0f;
#pragma unroll
    for (int s = 0; s < 32; s++) {
        out += __shfl_sync(0xFFFFFFFFu, c[s] * ws, (lane - s) & 31);
    }

    const int attoff = (2 - u) * 128;   // att layout [T|A|V]
    g_attp[(size_t)jq * (NROWS * 384) + (size_t)n * 384 + attoff + t] = out;
}

// ---------------------------------------------------------------------------
// Kernel 2b: sum the four j-quarter partials, emit att hi/lo bf16 planes.
// 4 elements per thread, float4 loads, STG.64 stores.
// ---------------------------------------------------------------------------
__global__ __launch_bounds__(256)
void att_fix_kernel() {
    const int i4 = (blockIdx.x * 256 + threadIdx.x) * 4;   // over NROWS*384
    const int S = NROWS * 384;
    float4 a = *(const float4*)&g_attp[i4];
    float4 b = *(const float4*)&g_attp[i4 + S];
    float4 c = *(const float4*)&g_attp[i4 + 2 * S];
    float4 d = *(const float4*)&g_attp[i4 + 3 * S];
    float o[4] = { (a.x + b.x) + (c.x + d.x), (a.y + b.y) + (c.y + d.y),
                   (a.z + b.z) + (c.z + d.z), (a.w + b.w) + (c.w + d.w) };
    __nv_bfloat16 hi4[4], lo4[4];
#pragma unroll
    for (int e = 0; e < 4; e++) {
        __nv_bfloat16 hi = __float2bfloat16(o[e]);
        hi4[e] = hi;
        lo4[e] = __float2bfloat16(o[e] - __bfloat162float(hi));
    }
    *reinterpret_cast<uint2*>(&g_att_hi[i4]) = *reinterpret_cast<uint2*>(hi4);
    *reinterpret_cast<uint2*>(&g_att_lo[i4]) = *reinterpret_cast<uint2*>(lo4);
}

// ---------------------------------------------------------------------------
// Kernel 3: out = att @ Wln.T + bln (plain bf16 GEMM, K' = 1152)
// ---------------------------------------------------------------------------
__global__ __launch_bounds__(512, 2)
void out_mma_kernel(const float* __restrict__ bln, float* __restrict__ out) {
    gemm_bf16_128(g_att_hi, g_att_lo, 384, 384, g_wln, 1152,
                  out, 128, bln, blockIdx.x * 128, 0, 18);
}

// ---------------------------------------------------------------------------
// Input order: 0 g, 1 h, 2 WqT, 3 WkT, 4 WvT, 5 WqA, 6 WkA, 7 WvA,
//              8 WqV, 9 WkV, 10 WvV, 11 Wln, 12 bln
// ---------------------------------------------------------------------------
extern "C" void kernel_launch(void* const* d_in, const int* in_sizes, int n_in,
                              void* d_out, int out_size) {
    const float* h = (const float*)d_in[1];
    WPtrs wp;
    wp.w[0] = (const float*)d_in[8];   // WqV
    wp.w[1] = (const float*)d_in[9];   // WkV
    wp.w[2] = (const float*)d_in[10];  // WvV
    wp.w[3] = (const float*)d_in[5];   // WqA
    wp.w[4] = (const float*)d_in[6];   // WkA
    wp.w[5] = (const float*)d_in[7];   // WvA
    wp.w[6] = (const float*)d_in[2];   // WqT
    wp.w[7] = (const float*)d_in[3];   // WkT
    wp.w[8] = (const float*)d_in[4];   // WvT
    const float* Wln = (const float*)d_in[11];
    const float* bln = (const float*)d_in[12];

    conv_h_kernel<<<NROWS, 256>>>(h);
    conv_w_kernel<<<dim3(128, 10), 256>>>(wp, Wln);

    cudaFuncSetAttribute(qkv_mma_kernel, cudaFuncAttributeMaxDynamicSharedMemorySize,
                         GEMM_SMEM);
    qkv_mma_kernel<<<dim3(64, 9, 2), 512, GEMM_SMEM>>>();

    attn_kernel<<<dim3(NROWS, 3, 4), 128>>>();

    att_fix_kernel<<<(NROWS * 384) / 1024, 256>>>();

    cudaFuncSetAttribute(out_mma_kernel, cudaFuncAttributeMaxDynamicSharedMemorySize,
                         GEMM_SMEM);
    out_mma_kernel<<<64, 512, GEMM_SMEM>>>(bln, (float*)d_out);
}

// round 12
// speedup vs baseline: 1.3400x; 1.0697x over previous
#include <cuda_runtime.h>
#include <cuda_bf16.h>
#include <cstdint>
#include <cstddef>

#define NROWS 8192
#define INDIM 2029
#define HW 2112   // padded plane width: 128(T) + 384(A) + 1600(V)

// Scratch (device globals — no allocation allowed)
__device__ __align__(16) __nv_bfloat16 g_h_hi[NROWS * HW];
__device__ __align__(16) __nv_bfloat16 g_h_lo[NROWS * HW];
__device__ __align__(16) __nv_bfloat16 g_ws[9 * 128 * 4800];   // per-seg B' = [bh|bh|bl]
__device__ __align__(16) __nv_bfloat16 g_wln[128 * 1152];      // Wln B' = [bh|bh|bl]
__device__ float g_qkv[NROWS * 1152];                          // [n][Vq Vk Vv Aq Ak Av Tq Tk Tv]
__device__ float g_qkv2[NROWS * 384];                          // V segs, K-chunks [38,75) partial
__device__ __align__(16) float g_attp[4 * NROWS * 384];        // j-quarter partials of att
__device__ __align__(16) __nv_bfloat16 g_att_hi[NROWS * 384];  // [n][T|A|V] hi
__device__ __align__(16) __nv_bfloat16 g_att_lo[NROWS * 384];  // [n][T|A|V] lo

struct WPtrs { const float* w[9]; };

__device__ __forceinline__ float ex2f(float x) {
    float r; asm("ex2.approx.f32 %0, %1;" : "=f"(r) : "f"(x)); return r;
}
__device__ __forceinline__ uint32_t smem_u32(const void* p) {
    uint32_t a;
    asm("{ .reg .u64 t; cvta.to.shared.u64 t, %1; cvt.u32.u64 %0, t; }" : "=r"(a) : "l"(p));
    return a;
}
__device__ __forceinline__ void mma16816(float* c, const uint32_t* a, const uint32_t* b) {
    asm volatile(
        "mma.sync.aligned.m16n8k16.row.col.f32.bf16.bf16.f32 "
        "{%0,%1,%2,%3}, {%4,%5,%6,%7}, {%8,%9}, {%0,%1,%2,%3};"
        : "+f"(c[0]), "+f"(c[1]), "+f"(c[2]), "+f"(c[3])
        : "r"(a[0]), "r"(a[1]), "r"(a[2]), "r"(a[3]), "r"(b[0]), "r"(b[1]));
}
__device__ __forceinline__ void ldsm_x4(uint32_t* r, uint32_t addr) {
    asm volatile("ldmatrix.sync.aligned.m8n8.x4.shared.b16 {%0,%1,%2,%3}, [%4];"
        : "=r"(r[0]), "=r"(r[1]), "=r"(r[2]), "=r"(r[3]) : "r"(addr));
}
__device__ __forceinline__ void cp16(uint32_t d, const void* s) {
    asm volatile("cp.async.cg.shared.global [%0], [%1], 16;" :: "r"(d), "l"(s));
}
__device__ __forceinline__ void cp_commit() { asm volatile("cp.async.commit_group;" ::: "memory"); }
__device__ __forceinline__ void cp_wait1()  { asm volatile("cp.async.wait_group 1;" ::: "memory"); }

// ---------------------------------------------------------------------------
// Precompute: h -> per-unit hi/lo bf16 planes (zero-padded widths 128/384/1600)
// 4 cols per thread; STG.64 stores.
// ---------------------------------------------------------------------------
__global__ __launch_bounds__(256)
void conv_h_kernel(const float* __restrict__ h) {
    const int n = blockIdx.x;
    const float* hrow = h + (size_t)n * INDIM;
    for (int g = threadIdx.x; g < HW / 4; g += 256) {
        const int col = g * 4;
        int off, local0, F;
        if (col < 128)      { off = 0;   local0 = col;       F = 100; }
        else if (col < 512) { off = 100; local0 = col - 128; F = 342; }
        else                { off = 442; local0 = col - 512; F = 1587; }
        __nv_bfloat16 hi4[4], lo4[4];
#pragma unroll
        for (int e = 0; e < 4; e++) {
            int lc = local0 + e;
            float v = (lc < F) ? __ldg(hrow + off + lc) : 0.0f;
            __nv_bfloat16 hi = __float2bfloat16(v);
            hi4[e] = hi;
            lo4[e] = __float2bfloat16(v - __bfloat162float(hi));
        }
        *reinterpret_cast<uint2*>(&g_h_hi[(size_t)n * HW + col]) = *reinterpret_cast<uint2*>(hi4);
        *reinterpret_cast<uint2*>(&g_h_lo[(size_t)n * HW + col]) = *reinterpret_cast<uint2*>(lo4);
    }
}

// ---------------------------------------------------------------------------
// Precompute weights: B' = [bh | bh | bl] per seg (and Wln as seg 9)
// ---------------------------------------------------------------------------
__global__ __launch_bounds__(256)
void conv_w_kernel(WPtrs wp, const float* __restrict__ Wln) {
    const int Fs[10]  = {1587,1587,1587, 342,342,342, 100,100,100, 384};
    const int Fps[10] = {1600,1600,1600, 384,384,384, 128,128,128, 384};
    const int d = blockIdx.x, t = blockIdx.y;
    const int F = Fs[t], Fp = Fps[t];
    const float* W = (t < 9) ? wp.w[t] : Wln;
    __nv_bfloat16* dst = (t < 9) ? (g_ws + (size_t)t * 128 * 4800 + (size_t)d * 3 * Fp)
                                 : (g_wln + (size_t)d * 1152);
    for (int k = threadIdx.x; k < 3 * Fp; k += 256) {
        int p = k / Fp, col = k - p * Fp;
        float v = (col < F) ? __ldg(W + (size_t)d * F + col) : 0.0f;
        __nv_bfloat16 hi = __float2bfloat16(v);
        if (p == 2) dst[k] = __float2bfloat16(v - __bfloat162float(hi));
        else        dst[k] = hi;
    }
}

// ---------------------------------------------------------------------------
// Plain bf16 GEMM, 512 threads: C[128 x 128] = A'[128 x 3Kp] * B'[128 x 3Kp]^T
// (+ bias), over chunk range [c0, c1). A' planes: [hi | lo | hi] (selected in
// loader); B' physically [bh|bh|bl]. 16 warps, warp tile 32x32 (acc = 32 regs).
// cp.async 3-stage pipeline, ldmatrix fragments, smem row stride 144B.
// ---------------------------------------------------------------------------
#define ROWB 144
#define TILEB (128 * ROWB)
#define STAGEB (2 * TILEB)
#define GEMM_SMEM (3 * STAGEB)   // 110592

__device__ __forceinline__ void gemm_bf16_128(
    const __nv_bfloat16* __restrict__ Ahi, const __nv_bfloat16* __restrict__ Alo,
    int sA, int Kp,
    const __nv_bfloat16* __restrict__ B, int ldb,
    float* __restrict__ C, int ldc, const float* __restrict__ bias, int n0,
    int c0, int c1)
{
    extern __shared__ __align__(16) char dsm[];
    const uint32_t sbase = smem_u32(dsm);
    const int tid = threadIdx.x;
    const int lane = tid & 31, wid = tid >> 5;       // 16 warps
    const int wm = wid & 3, wn = wid >> 2;           // 4 x 4 warp grid
    const int g4 = lane >> 2, tq = lane & 3;
    const int lr = tid >> 2;                          // loader row 0..127
    const int q4 = tid & 3;                           // loader quarter

    const int Kc = Kp >> 6;      // 64-wide chunks per plane
    const int NC = c1 - c0;

    // ldmatrix lane-address components (x4: rows of two 8x8 pairs + klo/khi)
    const uint32_t a_off = (uint32_t)(wm * 32 + ((lane >> 3) & 1) * 8 + (lane & 7)) * ROWB
                           + ((lane >> 4) & 1) * 16;
    const uint32_t b_off = (uint32_t)(wn * 32 + ((lane >> 4) & 1) * 8 + (lane & 7)) * ROWB
                           + ((lane >> 3) & 1) * 16;

    float acc[2][4][4];
#pragma unroll
    for (int t = 0; t < 2; t++)
#pragma unroll
        for (int nt = 0; nt < 4; nt++)
#pragma unroll
            for (int i = 0; i < 4; i++) acc[t][nt][i] = 0.0f;

    auto issue = [&](int c, int st) {
        int pk = c / Kc;
        int cb = (c - pk * Kc) << 6;
        const __nv_bfloat16* As = ((pk == 1) ? Alo : Ahi)
                                  + (size_t)(n0 + lr) * sA + cb + q4 * 16;
        const __nv_bfloat16* Bs = B + (size_t)lr * ldb + (c << 6) + q4 * 16;
        uint32_t ab = sbase + st * STAGEB + lr * ROWB + q4 * 32;
        uint32_t bb = ab + TILEB;
#pragma unroll
        for (int i = 0; i < 2; i++) {
            cp16(ab + i * 16, As + i * 8);
            cp16(bb + i * 16, Bs + i * 8);
        }
        cp_commit();
    };

    issue(c0, 0);
    if (NC > 1) issue(c0 + 1, 1); else cp_commit();

    for (int ci = 0; ci < NC; ci++) {
        cp_wait1();
        __syncthreads();

        const uint32_t sa = sbase + (ci % 3) * STAGEB;
        const uint32_t aaddr = sa + a_off;
        const uint32_t baddr = sa + TILEB + b_off;
#pragma unroll
        for (int kk = 0; kk < 4; kk++) {
            uint32_t a[2][4], b[2][4];
            ldsm_x4(a[0], aaddr + kk * 32);
            ldsm_x4(a[1], aaddr + 16 * ROWB + kk * 32);
            ldsm_x4(b[0], baddr + kk * 32);
            ldsm_x4(b[1], baddr + 16 * ROWB + kk * 32);
#pragma unroll
            for (int nt = 0; nt < 4; nt++) {
                mma16816(acc[0][nt], a[0], b[nt >> 1] + (nt & 1) * 2);
                mma16816(acc[1][nt], a[1], b[nt >> 1] + (nt & 1) * 2);
            }
        }

        if (ci + 2 < NC) issue(c0 + ci + 2, (ci + 2) % 3);
        else cp_commit();   // empty group keeps wait_group bookkeeping consistent
    }

#pragma unroll
    for (int t = 0; t < 2; t++)
#pragma unroll
        for (int nt = 0; nt < 4; nt++) {
            int gm = n0 + wm * 32 + t * 16 + g4;
            int gn = wn * 32 + nt * 8 + tq * 2;
            float bx = 0.0f, by = 0.0f;
            if (bias) { bx = __ldg(bias + gn); by = __ldg(bias + gn + 1); }
            float2 v0 = make_float2(acc[t][nt][0] + bx, acc[t][nt][1] + by);
            float2 v1 = make_float2(acc[t][nt][2] + bx, acc[t][nt][3] + by);
            *(float2*)(C + (size_t)gm * ldc + gn) = v0;
            *(float2*)(C + (size_t)(gm + 8) * ldc + gn) = v1;
        }
}

// ---------------------------------------------------------------------------
// Kernel 1: QKV projections. V segs (s<3) split in K over blockIdx.z:
// z=0 -> chunks [0,38) into g_qkv; z=1 -> chunks [38,75) into g_qkv2.
// ---------------------------------------------------------------------------
__global__ __launch_bounds__(512, 2)
void qkv_mma_kernel() {
    const int Fps[9] = {1600,1600,1600, 384,384,384, 128,128,128};
    const int ub[9]  = { 512, 512, 512, 128,128,128,   0,  0,  0};
    const int s = blockIdx.y, z = blockIdx.z;
    const int Fp = Fps[s];
    const int NC = 3 * (Fp >> 6);

    int c0 = 0, c1 = NC, ldc = 1152;
    float* C = g_qkv + s * 128;
    if (s < 3) {
        if (z == 0) c1 = 38;
        else { c0 = 38; C = g_qkv2 + s * 128; ldc = 384; }
    } else if (z == 1) {
        return;
    }
    gemm_bf16_128(g_h_hi + ub[s], g_h_lo + ub[s], HW, Fp,
                  g_ws + (size_t)s * 128 * 4800, 3 * Fp,
                  C, ldc, nullptr, blockIdx.x * 128, c0, c1);
}

// ---------------------------------------------------------------------------
// Kernel 2: attention with register-resident E, XOR-butterfly transpose.
// Block = (n, u, jq): 32 columns. Warp w's 32x32 block: lane j computes
// c[s] = E[j^s][j] via qi = shfl_xor(q, s); column Z is lane-local;
// out_r = sum_s shfl_xor(c[s] * w, s)  (= E[r][r^s] * w_{r^s}, full coverage).
// All SHFL.BFLY lanemasks are immediates: no index ALU at all.
// ---------------------------------------------------------------------------
__global__ __launch_bounds__(128)
void attn_kernel() {
    __shared__ float zp[128];

    const int n  = blockIdx.x;
    const int u  = blockIdx.y;   // 0=V, 1=A, 2=T (qkv seg order)
    const int jq = blockIdx.z;   // j in [jq*32, jq*32+32)
    const int t    = threadIdx.x;
    const int lane = t & 31;

    const float* base  = g_qkv  + (size_t)n * 1152 + u * 384;
    const float* base2 = g_qkv2 + (size_t)n * 384;

    // log2(e) / sqrt(128)
    const float scale = 1.4426950408889634f / 11.313708498984761f;
    float qraw = base[t];                      // q for row i = t
    float kraw = base[128 + jq * 32 + lane];   // k for column j = jq*32+lane
    float vraw = base[256 + jq * 32 + lane];   // v for column j
    if (u == 0) {
        qraw += base2[t];
        kraw += base2[128 + jq * 32 + lane];
        vraw += base2[256 + jq * 32 + lane];
    }
    const float qown = qraw * scale;

    // Phase 1: lane's column over the warp stripe, XOR row order:
    // c[s] = E[(lane^s) within stripe][lane], plus lane-local column Z.
    float c[32];
    float z = 0.0f;
#pragma unroll
    for (int s = 0; s < 32; s++) {
        float qi = __shfl_xor_sync(0xFFFFFFFFu, qown, s);
        float e = ex2f(qi * kraw);
        c[s] = e;
        z += e;
    }
    zp[t] = z;
    __syncthreads();

    // Full column Z (4 stripe partials), lane-local w_j = v_j / Z_j
    float Z = (zp[lane] + zp[lane + 32]) + (zp[lane + 64] + zp[lane + 96]);
    const float ws = vraw / Z;

    // Phase 2: butterfly transpose-sum: round s delivers E[r][r^s]*w_{r^s}.
    float out = 0.0f;
#pragma unroll
    for (int s = 0; s < 32; s++) {
        out += __shfl_xor_sync(0xFFFFFFFFu, c[s] * ws, s);
    }

    const int attoff = (2 - u) * 128;   // att layout [T|A|V]
    g_attp[(size_t)jq * (NROWS * 384) + (size_t)n * 384 + attoff + t] = out;
}

// ---------------------------------------------------------------------------
// Kernel 2b: sum the four j-quarter partials, emit att hi/lo bf16 planes.
// 4 elements per thread, float4 loads, STG.64 stores.
// ---------------------------------------------------------------------------
__global__ __launch_bounds__(256)
void att_fix_kernel() {
    const int i4 = (blockIdx.x * 256 + threadIdx.x) * 4;   // over NROWS*384
    const int S = NROWS * 384;
    float4 a = *(const float4*)&g_attp[i4];
    float4 b = *(const float4*)&g_attp[i4 + S];
    float4 c = *(const float4*)&g_attp[i4 + 2 * S];
    float4 d = *(const float4*)&g_attp[i4 + 3 * S];
    float o[4] = { (a.x + b.x) + (c.x + d.x), (a.y + b.y) + (c.y + d.y),
                   (a.z + b.z) + (c.z + d.z), (a.w + b.w) + (c.w + d.w) };
    __nv_bfloat16 hi4[4], lo4[4];
#pragma unroll
    for (int e = 0; e < 4; e++) {
        __nv_bfloat16 hi = __float2bfloat16(o[e]);
        hi4[e] = hi;
        lo4[e] = __float2bfloat16(o[e] - __bfloat162float(hi));
    }
    *reinterpret_cast<uint2*>(&g_att_hi[i4]) = *reinterpret_cast<uint2*>(hi4);
    *reinterpret_cast<uint2*>(&g_att_lo[i4]) = *reinterpret_cast<uint2*>(lo4);
}

// ---------------------------------------------------------------------------
// Kernel 3: out = att @ Wln.T + bln (plain bf16 GEMM, K' = 1152)
// ---------------------------------------------------------------------------
__global__ __launch_bounds__(512, 2)
void out_mma_kernel(const float* __restrict__ bln, float* __restrict__ out) {
    gemm_bf16_128(g_att_hi, g_att_lo, 384, 384, g_wln, 1152,
                  out, 128, bln, blockIdx.x * 128, 0, 18);
}

// ---------------------------------------------------------------------------
// Input order: 0 g, 1 h, 2 WqT, 3 WkT, 4 WvT, 5 WqA, 6 WkA, 7 WvA,
//              8 WqV, 9 WkV, 10 WvV, 11 Wln, 12 bln
// ---------------------------------------------------------------------------
extern "C" void kernel_launch(void* const* d_in, const int* in_sizes, int n_in,
                              void* d_out, int out_size) {
    const float* h = (const float*)d_in[1];
    WPtrs wp;
    wp.w[0] = (const float*)d_in[8];   // WqV
    wp.w[1] = (const float*)d_in[9];   // WkV
    wp.w[2] = (const float*)d_in[10];  // WvV
    wp.w[3] = (const float*)d_in[5];   // WqA
    wp.w[4] = (const float*)d_in[6];   // WkA
    wp.w[5] = (const float*)d_in[7];   // WvA
    wp.w[6] = (const float*)d_in[2];   // WqT
    wp.w[7] = (const float*)d_in[3];   // WkT
    wp.w[8] = (const float*)d_in[4];   // WvT
    const float* Wln = (const float*)d_in[11];
    const float* bln = (const float*)d_in[12];

    conv_h_kernel<<<NROWS, 256>>>(h);
    conv_w_kernel<<<dim3(128, 10), 256>>>(wp, Wln);

    cudaFuncSetAttribute(qkv_mma_kernel, cudaFuncAttributeMaxDynamicSharedMemorySize,
                         GEMM_SMEM);
    qkv_mma_kernel<<<dim3(64, 9, 2), 512, GEMM_SMEM>>>();

    attn_kernel<<<dim3(NROWS, 3, 4), 128>>>();

    att_fix_kernel<<<(NROWS * 384) / 1024, 256>>>();

    cudaFuncSetAttribute(out_mma_kernel, cudaFuncAttributeMaxDynamicSharedMemorySize,
                         GEMM_SMEM);
    out_mma_kernel<<<64, 512, GEMM_SMEM>>>(bln, (float*)d_out);
}